// round 3
// baseline (speedup 1.0000x reference)
#include <cuda_runtime.h>
#include <math.h>

// ---------------------------------------------------------------------------
// Problem constants (shapes fixed by the dataset): N=50000, E=800000, D=128
// ---------------------------------------------------------------------------
#define MAXN 50176
#define MAXE 800000

// Scratch (allowed: __device__ globals, no allocation)
__device__ float g_h1  [(size_t)MAXN * 256];   // x @ W1      [N, 2*128]
__device__ float g_out1[(size_t)MAXN * 256];   // elu(gat1)   [N, 256]
__device__ float g_h2  [(size_t)MAXN * 128];   // out1 @ W2   [N, 128]
__device__ float g_out2[(size_t)MAXN * 128];   // elu(gat2)   [N, 128]
__device__ float g_h3  [(size_t)MAXN * 128];   // relu(mlp1)  [N, 128]
__device__ float g_as1 [(size_t)MAXN * 2];
__device__ float g_ad1 [(size_t)MAXN * 2];
__device__ float g_as2 [MAXN];
__device__ float g_ad2 [MAXN];
__device__ int   g_cnt [MAXN];
__device__ int   g_base[MAXN];
__device__ int   g_cur [MAXN];
__device__ int   g_srcs[MAXE];

// ---------------------------------------------------------------------------
// helpers
// ---------------------------------------------------------------------------
__device__ __forceinline__ float lrelu(float v) { return v > 0.f ? v : 0.2f * v; }
__device__ __forceinline__ float elu_f(float v) { return v > 0.f ? v : expm1f(v); }

// ---------------------------------------------------------------------------
// CSR build: histogram -> exclusive scan (1 block) -> scatter
// ---------------------------------------------------------------------------
__global__ void zero_counts(int* cnt, int* cur, int Nn) {
    int i = blockIdx.x * blockDim.x + threadIdx.x;
    if (i < Nn) { cnt[i] = 0; cur[i] = 0; }
}

__global__ void hist_kernel(const int* __restrict__ ei, int E, int* cnt) {
    int i = blockIdx.x * blockDim.x + threadIdx.x;
    if (i < E) atomicAdd(&cnt[ei[E + i]], 1);
}

__global__ void scan_kernel(const int* __restrict__ cnt, int* __restrict__ base, int Nn) {
    __shared__ int partial[1024];
    int tid = threadIdx.x;
    int per = (Nn + 1023) / 1024;
    int begin = tid * per;
    int end = begin + per; if (end > Nn) end = Nn;
    int sum = 0;
    for (int i = begin; i < end; i++) sum += cnt[i];
    partial[tid] = sum;
    __syncthreads();
    // Hillis-Steele inclusive scan
    for (int off = 1; off < 1024; off <<= 1) {
        int v = (tid >= off) ? partial[tid - off] : 0;
        __syncthreads();
        partial[tid] += v;
        __syncthreads();
    }
    int run = (tid == 0) ? 0 : partial[tid - 1];
    for (int i = begin; i < end; i++) { base[i] = run; run += cnt[i]; }
}

__global__ void scatter_kernel(const int* __restrict__ ei, int E,
                               const int* __restrict__ base, int* cur,
                               int* __restrict__ srcs) {
    int i = blockIdx.x * blockDim.x + threadIdx.x;
    if (i < E) {
        int s = ei[i];
        int d = ei[E + i];
        int pos = base[d] + atomicAdd(&cur[d], 1);
        srcs[pos] = s;
    }
}

// ---------------------------------------------------------------------------
// Tiled fp32 GEMM: C[M,N] = A[M,K] @ B[K,N]  (+ optional bias, relu)
// BM=128 BN=64 BK=16, TM=8 TN=4, 256 threads. N,K multiples of {64,16}.
// ---------------------------------------------------------------------------
#define GBM 128
#define GBN 64
#define GBK 16
__global__ __launch_bounds__(256) void gemm_tiled(
    const float* __restrict__ A, const float* __restrict__ B,
    const float* __restrict__ bias, float* __restrict__ C,
    int M, int N, int K, int act)
{
    __shared__ float As[GBK * GBM];
    __shared__ float Bs[GBK * GBN];
    int tid = threadIdx.x;
    int cRow = blockIdx.y, cCol = blockIdx.x;

    int threadRow = tid / 16;          // 0..15 -> 8 rows each
    int threadCol = tid % 16;          // 0..15 -> 4 cols each

    int innerRowA = tid / 4;           // 0..63
    int innerColA = tid % 4;           // 0..3  (float4 along K)
    int innerRowB = tid / 16;          // 0..15
    int innerColB = tid % 16;          // 0..15 (float4 along N)

    const float* Bb = B + cCol * GBN;
    int r0 = cRow * GBM + innerRowA;
    int r1 = r0 + 64;

    float acc[8][4];
    #pragma unroll
    for (int i = 0; i < 8; i++)
        #pragma unroll
        for (int j = 0; j < 4; j++) acc[i][j] = 0.f;

    for (int k0 = 0; k0 < K; k0 += GBK) {
        float4 a0 = make_float4(0, 0, 0, 0), a1 = make_float4(0, 0, 0, 0);
        if (r0 < M) a0 = *(const float4*)&A[(size_t)r0 * K + k0 + innerColA * 4];
        if (r1 < M) a1 = *(const float4*)&A[(size_t)r1 * K + k0 + innerColA * 4];
        As[(innerColA * 4 + 0) * GBM + innerRowA] = a0.x;
        As[(innerColA * 4 + 1) * GBM + innerRowA] = a0.y;
        As[(innerColA * 4 + 2) * GBM + innerRowA] = a0.z;
        As[(innerColA * 4 + 3) * GBM + innerRowA] = a0.w;
        As[(innerColA * 4 + 0) * GBM + innerRowA + 64] = a1.x;
        As[(innerColA * 4 + 1) * GBM + innerRowA + 64] = a1.y;
        As[(innerColA * 4 + 2) * GBM + innerRowA + 64] = a1.z;
        As[(innerColA * 4 + 3) * GBM + innerRowA + 64] = a1.w;
        float4 b4 = *(const float4*)&Bb[(size_t)(k0 + innerRowB) * N + innerColB * 4];
        *(float4*)&Bs[innerRowB * GBN + innerColB * 4] = b4;
        __syncthreads();

        #pragma unroll
        for (int k = 0; k < GBK; k++) {
            float4 m0 = *(const float4*)&As[k * GBM + threadRow * 8];
            float4 m1 = *(const float4*)&As[k * GBM + threadRow * 8 + 4];
            float4 n0 = *(const float4*)&Bs[k * GBN + threadCol * 4];
            float rm[8] = {m0.x, m0.y, m0.z, m0.w, m1.x, m1.y, m1.z, m1.w};
            float rn[4] = {n0.x, n0.y, n0.z, n0.w};
            #pragma unroll
            for (int i = 0; i < 8; i++)
                #pragma unroll
                for (int j = 0; j < 4; j++) acc[i][j] += rm[i] * rn[j];
        }
        __syncthreads();
    }

    int c0 = cCol * GBN + threadCol * 4;
    #pragma unroll
    for (int i = 0; i < 8; i++) {
        int r = cRow * GBM + threadRow * 8 + i;
        if (r < M) {
            float4 v;
            v.x = acc[i][0]; v.y = acc[i][1]; v.z = acc[i][2]; v.w = acc[i][3];
            if (bias) {
                float4 b = *(const float4*)&bias[c0];
                v.x += b.x; v.y += b.y; v.z += b.z; v.w += b.w;
            }
            if (act == 1) {
                v.x = fmaxf(v.x, 0.f); v.y = fmaxf(v.y, 0.f);
                v.z = fmaxf(v.z, 0.f); v.w = fmaxf(v.w, 0.f);
            }
            *(float4*)&C[(size_t)r * N + c0] = v;
        }
    }
}

// ---------------------------------------------------------------------------
// Final GEMM: C[M,8] = relu(A[M,K] @ B[K,8] + bias). One warp per row.
// ---------------------------------------------------------------------------
__global__ void gemm_n8(const float* __restrict__ A, const float* __restrict__ B,
                        const float* __restrict__ bias, float* __restrict__ C,
                        int M, int K)
{
    int w = (blockIdx.x * blockDim.x + threadIdx.x) >> 5;
    int lane = threadIdx.x & 31;
    if (w >= M) return;
    float a0=0,a1=0,a2=0,a3=0,a4=0,a5=0,a6=0,a7=0;
    for (int k = lane; k < K; k += 32) {
        float a = A[(size_t)w * K + k];
        const float4* bp = (const float4*)(B + k * 8);
        float4 b0 = bp[0], b1 = bp[1];
        a0 += a * b0.x; a1 += a * b0.y; a2 += a * b0.z; a3 += a * b0.w;
        a4 += a * b1.x; a5 += a * b1.y; a6 += a * b1.z; a7 += a * b1.w;
    }
    #pragma unroll
    for (int off = 16; off; off >>= 1) {
        a0 += __shfl_xor_sync(0xffffffffu, a0, off);
        a1 += __shfl_xor_sync(0xffffffffu, a1, off);
        a2 += __shfl_xor_sync(0xffffffffu, a2, off);
        a3 += __shfl_xor_sync(0xffffffffu, a3, off);
        a4 += __shfl_xor_sync(0xffffffffu, a4, off);
        a5 += __shfl_xor_sync(0xffffffffu, a5, off);
        a6 += __shfl_xor_sync(0xffffffffu, a6, off);
        a7 += __shfl_xor_sync(0xffffffffu, a7, off);
    }
    if (lane == 0) {
        float* o = C + (size_t)w * 8;
        o[0] = fmaxf(a0 + bias[0], 0.f); o[1] = fmaxf(a1 + bias[1], 0.f);
        o[2] = fmaxf(a2 + bias[2], 0.f); o[3] = fmaxf(a3 + bias[3], 0.f);
        o[4] = fmaxf(a4 + bias[4], 0.f); o[5] = fmaxf(a5 + bias[5], 0.f);
        o[6] = fmaxf(a6 + bias[6], 0.f); o[7] = fmaxf(a7 + bias[7], 0.f);
    }
}

// ---------------------------------------------------------------------------
// attention dot products: asrc[n,h] = h[n,h,:].att_src[h,:], adst likewise.
// One warp per node; heads in {1,2}, feature width 128 per head.
// ---------------------------------------------------------------------------
__global__ void attn_dots(const float* __restrict__ hfeat,
                          const float* __restrict__ attS, const float* __restrict__ attD,
                          float* __restrict__ asrc, float* __restrict__ adst,
                          int Nn, int heads)
{
    int w = (blockIdx.x * blockDim.x + threadIdx.x) >> 5;
    int lane = threadIdx.x & 31;
    if (w >= Nn) return;
    const float4* row = (const float4*)(hfeat + (size_t)w * heads * 128);
    for (int hd = 0; hd < heads; hd++) {
        float4 v  = row[hd * 32 + lane];
        float4 s4 = ((const float4*)attS)[hd * 32 + lane];
        float4 d4 = ((const float4*)attD)[hd * 32 + lane];
        float ps = v.x * s4.x + v.y * s4.y + v.z * s4.z + v.w * s4.w;
        float pd = v.x * d4.x + v.y * d4.y + v.z * d4.z + v.w * d4.w;
        #pragma unroll
        for (int off = 16; off; off >>= 1) {
            ps += __shfl_xor_sync(0xffffffffu, ps, off);
            pd += __shfl_xor_sync(0xffffffffu, pd, off);
        }
        if (lane == 0) {
            asrc[w * heads + hd] = ps;
            adst[w * heads + hd] = pd;
        }
    }
}

// ---------------------------------------------------------------------------
// GAT aggregation, 2 heads, 128 feat/head (layer 1). One warp per dst node.
// Self-loop handled implicitly. Epilogue: +bias, ELU.
// ---------------------------------------------------------------------------
__global__ void agg_gat_h2(const float* __restrict__ hfeat,
                           const float* __restrict__ asrc, const float* __restrict__ adst,
                           const int* __restrict__ srcs, const int* __restrict__ base,
                           const int* __restrict__ cnt, const float* __restrict__ bias,
                           float* __restrict__ out, int Nn)
{
    int n = (blockIdx.x * blockDim.x + threadIdx.x) >> 5;
    int lane = threadIdx.x & 31;
    if (n >= Nn) return;
    int st = base[n], deg = cnt[n];
    float ad0 = adst[2 * n], ad1 = adst[2 * n + 1];

    // pass A: per-head max over edges (lanes stride), then self-loop
    float m0 = -1e30f, m1 = -1e30f;
    for (int k = lane; k < deg; k += 32) {
        int s = srcs[st + k];
        float2 as = *(const float2*)(asrc + 2 * s);
        m0 = fmaxf(m0, lrelu(as.x + ad0));
        m1 = fmaxf(m1, lrelu(as.y + ad1));
    }
    #pragma unroll
    for (int off = 16; off; off >>= 1) {
        m0 = fmaxf(m0, __shfl_xor_sync(0xffffffffu, m0, off));
        m1 = fmaxf(m1, __shfl_xor_sync(0xffffffffu, m1, off));
    }
    float2 asn = *(const float2*)(asrc + 2 * n);
    float es0 = lrelu(asn.x + ad0), es1 = lrelu(asn.y + ad1);
    m0 = fmaxf(m0, es0); m1 = fmaxf(m1, es1);

    // pass B: weighted sum; lane covers 4 cols of head0 + 4 cols of head1
    float den0 = 0.f, den1 = 0.f;
    float x0=0,x1=0,x2=0,x3=0, y0=0,y1=0,y2=0,y3=0;
    for (int k = 0; k < deg; k++) {
        int s = __ldg(&srcs[st + k]);
        float2 as = *(const float2*)(asrc + 2 * s);
        float w0 = expf(lrelu(as.x + ad0) - m0);
        float w1 = expf(lrelu(as.y + ad1) - m1);
        den0 += w0; den1 += w1;
        const float4* r = (const float4*)(hfeat + (size_t)s * 256);
        float4 v0 = r[lane];
        float4 v1 = r[32 + lane];
        x0 += w0 * v0.x; x1 += w0 * v0.y; x2 += w0 * v0.z; x3 += w0 * v0.w;
        y0 += w1 * v1.x; y1 += w1 * v1.y; y2 += w1 * v1.z; y3 += w1 * v1.w;
    }
    {   // self loop
        float w0 = expf(es0 - m0), w1 = expf(es1 - m1);
        den0 += w0; den1 += w1;
        const float4* r = (const float4*)(hfeat + (size_t)n * 256);
        float4 v0 = r[lane];
        float4 v1 = r[32 + lane];
        x0 += w0 * v0.x; x1 += w0 * v0.y; x2 += w0 * v0.z; x3 += w0 * v0.w;
        y0 += w1 * v1.x; y1 += w1 * v1.y; y2 += w1 * v1.z; y3 += w1 * v1.w;
    }
    float i0 = 1.f / fmaxf(den0, 1e-16f);
    float i1 = 1.f / fmaxf(den1, 1e-16f);
    float4 b0 = ((const float4*)bias)[lane];
    float4 b1 = ((const float4*)bias)[32 + lane];
    float4 o0, o1;
    o0.x = elu_f(x0 * i0 + b0.x); o0.y = elu_f(x1 * i0 + b0.y);
    o0.z = elu_f(x2 * i0 + b0.z); o0.w = elu_f(x3 * i0 + b0.w);
    o1.x = elu_f(y0 * i1 + b1.x); o1.y = elu_f(y1 * i1 + b1.y);
    o1.z = elu_f(y2 * i1 + b1.z); o1.w = elu_f(y3 * i1 + b1.w);
    float4* orow = (float4*)(out + (size_t)n * 256);
    orow[lane] = o0;
    orow[32 + lane] = o1;
}

// ---------------------------------------------------------------------------
// GAT aggregation, 1 head, 128 feat (layer 2). One warp per dst node.
// ---------------------------------------------------------------------------
__global__ void agg_gat_h1(const float* __restrict__ hfeat,
                           const float* __restrict__ asrc, const float* __restrict__ adst,
                           const int* __restrict__ srcs, const int* __restrict__ base,
                           const int* __restrict__ cnt, const float* __restrict__ bias,
                           float* __restrict__ out, int Nn)
{
    int n = (blockIdx.x * blockDim.x + threadIdx.x) >> 5;
    int lane = threadIdx.x & 31;
    if (n >= Nn) return;
    int st = base[n], deg = cnt[n];
    float ad = adst[n];

    float m = -1e30f;
    for (int k = lane; k < deg; k += 32) {
        int s = srcs[st + k];
        m = fmaxf(m, lrelu(asrc[s] + ad));
    }
    #pragma unroll
    for (int off = 16; off; off >>= 1)
        m = fmaxf(m, __shfl_xor_sync(0xffffffffu, m, off));
    float es = lrelu(asrc[n] + ad);
    m = fmaxf(m, es);

    float den = 0.f;
    float x0=0,x1=0,x2=0,x3=0;
    for (int k = 0; k < deg; k++) {
        int s = __ldg(&srcs[st + k]);
        float w = expf(lrelu(asrc[s] + ad) - m);
        den += w;
        float4 v = ((const float4*)(hfeat + (size_t)s * 128))[lane];
        x0 += w * v.x; x1 += w * v.y; x2 += w * v.z; x3 += w * v.w;
    }
    {   // self loop
        float w = expf(es - m);
        den += w;
        float4 v = ((const float4*)(hfeat + (size_t)n * 128))[lane];
        x0 += w * v.x; x1 += w * v.y; x2 += w * v.z; x3 += w * v.w;
    }
    float inv = 1.f / fmaxf(den, 1e-16f);
    float4 b = ((const float4*)bias)[lane];
    float4 o;
    o.x = elu_f(x0 * inv + b.x); o.y = elu_f(x1 * inv + b.y);
    o.z = elu_f(x2 * inv + b.z); o.w = elu_f(x3 * inv + b.w);
    ((float4*)(out + (size_t)n * 128))[lane] = o;
}

// ---------------------------------------------------------------------------
// launch
// ---------------------------------------------------------------------------
extern "C" void kernel_launch(void* const* d_in, const int* in_sizes, int n_in,
                              void* d_out, int out_size)
{
    const float* x        = (const float*)d_in[0];
    const int*   ei       = (const int*)  d_in[1];
    const float* W1       = (const float*)d_in[2];
    const float* att1_src = (const float*)d_in[3];
    const float* att1_dst = (const float*)d_in[4];
    const float* b1       = (const float*)d_in[5];
    const float* W2       = (const float*)d_in[6];
    const float* att2_src = (const float*)d_in[7];
    const float* att2_dst = (const float*)d_in[8];
    const float* b2       = (const float*)d_in[9];
    const float* Wm1      = (const float*)d_in[10];
    const float* bm1      = (const float*)d_in[11];
    const float* Wm2      = (const float*)d_in[12];
    const float* bm2      = (const float*)d_in[13];
    float* out = (float*)d_out;

    int Nn = in_sizes[0] / 128;
    int E  = in_sizes[1] / 2;

    // Resolve scratch symbol addresses once (first call = correctness run,
    // which happens before graph capture; no CUDA API calls during capture).
    static float *p_h1=nullptr,*p_out1,*p_h2,*p_out2,*p_h3,*p_as1,*p_ad1,*p_as2,*p_ad2;
    static int *p_cnt,*p_base,*p_cur,*p_srcs;
    if (!p_h1) {
        cudaGetSymbolAddress((void**)&p_h1,   g_h1);
        cudaGetSymbolAddress((void**)&p_out1, g_out1);
        cudaGetSymbolAddress((void**)&p_h2,   g_h2);
        cudaGetSymbolAddress((void**)&p_out2, g_out2);
        cudaGetSymbolAddress((void**)&p_h3,   g_h3);
        cudaGetSymbolAddress((void**)&p_as1,  g_as1);
        cudaGetSymbolAddress((void**)&p_ad1,  g_ad1);
        cudaGetSymbolAddress((void**)&p_as2,  g_as2);
        cudaGetSymbolAddress((void**)&p_ad2,  g_ad2);
        cudaGetSymbolAddress((void**)&p_cnt,  g_cnt);
        cudaGetSymbolAddress((void**)&p_base, g_base);
        cudaGetSymbolAddress((void**)&p_cur,  g_cur);
        cudaGetSymbolAddress((void**)&p_srcs, g_srcs);
    }

    int gN   = (Nn + 255) / 256;
    int gE   = (E + 255) / 256;
    int gWrp = (Nn + 7) / 8;          // 8 warps per 256-thread block

    // CSR build by dst
    zero_counts  <<<gN, 256>>>(p_cnt, p_cur, Nn);
    hist_kernel  <<<gE, 256>>>(ei, E, p_cnt);
    scan_kernel  <<<1, 1024>>>(p_cnt, p_base, Nn);
    scatter_kernel<<<gE, 256>>>(ei, E, p_base, p_cur, p_srcs);

    // Layer 1: GAT(128 -> 2x128, concat)
    {
        dim3 grid(256 / GBN, (Nn + GBM - 1) / GBM);
        gemm_tiled<<<grid, 256>>>(x, W1, nullptr, p_h1, Nn, 256, 128, 0);
    }
    attn_dots <<<gWrp, 256>>>(p_h1, att1_src, att1_dst, p_as1, p_ad1, Nn, 2);
    agg_gat_h2<<<gWrp, 256>>>(p_h1, p_as1, p_ad1, p_srcs, p_base, p_cnt, b1, p_out1, Nn);

    // Layer 2: GAT(256 -> 128, 1 head)
    {
        dim3 grid(128 / GBN, (Nn + GBM - 1) / GBM);
        gemm_tiled<<<grid, 256>>>(p_out1, W2, nullptr, p_h2, Nn, 128, 256, 0);
    }
    attn_dots <<<gWrp, 256>>>(p_h2, att2_src, att2_dst, p_as2, p_ad2, Nn, 1);
    agg_gat_h1<<<gWrp, 256>>>(p_h2, p_as2, p_ad2, p_srcs, p_base, p_cnt, b2, p_out2, Nn);

    // MLP head
    {
        dim3 grid(128 / GBN, (Nn + GBM - 1) / GBM);
        gemm_tiled<<<grid, 256>>>(p_out2, Wm1, bm1, p_h3, Nn, 128, 128, 1);
    }
    gemm_n8<<<gWrp, 256>>>(p_h3, Wm2, bm2, out, Nn, 128);
}

// round 5
// speedup vs baseline: 1.2927x; 1.2927x over previous
#include <cuda_runtime.h>
#include <math.h>

// ---------------------------------------------------------------------------
// Problem constants: N=50000, E=800000, D=128
// ---------------------------------------------------------------------------
#define MAXN 50176
#define MAXE 800000

__device__ float g_h1  [(size_t)MAXN * 256];
__device__ float g_out1[(size_t)MAXN * 256];
__device__ float g_h2  [(size_t)MAXN * 128];
__device__ float g_out2[(size_t)MAXN * 128];
__device__ float g_h3  [(size_t)MAXN * 128];
__device__ float g_as1 [(size_t)MAXN * 2];
__device__ float g_ad1 [(size_t)MAXN * 2];
__device__ float g_as2 [MAXN];
__device__ float g_ad2 [MAXN];
__device__ int   g_cnt [MAXN];
__device__ int   g_base[MAXN];
__device__ int   g_cur [MAXN];
__device__ int   g_srcs[MAXE];

__device__ __forceinline__ float lrelu(float v) { return v > 0.f ? v : 0.2f * v; }
__device__ __forceinline__ float elu_f(float v) { return v > 0.f ? v : expm1f(v); }
__device__ __forceinline__ unsigned tf32_of(float x) {
    unsigned u; asm("cvt.rna.tf32.f32 %0, %1;" : "=r"(u) : "f"(x)); return u;
}

// ---------------------------------------------------------------------------
// CSR build
// ---------------------------------------------------------------------------
__global__ void zero_counts(int* cnt, int* cur, int Nn) {
    int i = blockIdx.x * blockDim.x + threadIdx.x;
    if (i < Nn) { cnt[i] = 0; cur[i] = 0; }
}

__global__ void hist_kernel(const int* __restrict__ ei, int E, int* cnt) {
    int i = blockIdx.x * blockDim.x + threadIdx.x;
    if (i < E) atomicAdd(&cnt[ei[E + i]], 1);
}

__global__ void scan_kernel(const int* __restrict__ cnt, int* __restrict__ base, int Nn) {
    __shared__ int partial[1024];
    int tid = threadIdx.x;
    int per = (Nn + 1023) / 1024;
    int begin = tid * per;
    int end = begin + per; if (end > Nn) end = Nn;
    int sum = 0;
    for (int i = begin; i < end; i++) sum += cnt[i];
    partial[tid] = sum;
    __syncthreads();
    for (int off = 1; off < 1024; off <<= 1) {
        int v = (tid >= off) ? partial[tid - off] : 0;
        __syncthreads();
        partial[tid] += v;
        __syncthreads();
    }
    int run = (tid == 0) ? 0 : partial[tid - 1];
    for (int i = begin; i < end; i++) { base[i] = run; run += cnt[i]; }
}

__global__ void scatter_kernel(const int* __restrict__ ei, int E,
                               const int* __restrict__ base, int* cur,
                               int* __restrict__ srcs) {
    int i = blockIdx.x * blockDim.x + threadIdx.x;
    if (i < E) {
        int s = ei[i];
        int d = ei[E + i];
        int pos = base[d] + atomicAdd(&cur[d], 1);
        srcs[pos] = s;
    }
}

// ---------------------------------------------------------------------------
// TF32 tensor-core GEMM: C[M,N] = A[M,K] @ B[K,N] (+bias, +relu)
// BM=128 BN=64 BK=32; 8 warps (4 along M x 2 along N); warp tile 32x32
// = 2 (m16) x 4 (n8) mma.sync.m16n8k8 tiles. N%64==0, K%32==0.
// ---------------------------------------------------------------------------
#define ASTR 36   // padded row stride (floats) for A smem: conflict-free frag LDS
#define BSTR 72   // padded row stride (floats) for B smem

__global__ __launch_bounds__(256) void gemm_tf32(
    const float* __restrict__ A, const float* __restrict__ B,
    const float* __restrict__ bias, float* __restrict__ C,
    int M, int N, int K, int act)
{
    __shared__ float As[128 * ASTR];   // 18432 B
    __shared__ float Bs[32 * BSTR];    //  9216 B

    int tid  = threadIdx.x;
    int lane = tid & 31;
    int warp = tid >> 5;
    int wm = warp >> 1;          // 0..3
    int wn = warp & 1;           // 0..1
    int grp = lane >> 2;         // 0..7
    int tig = lane & 3;          // 0..3

    int blockM = blockIdx.y * 128;
    int blockN = blockIdx.x * 64;

    // global-load assignment
    int ar  = tid >> 1;          // 0..127 (A row within tile)
    int ac0 = (tid & 1) * 16;    // A col base (16 floats each)
    int brow = tid >> 3;         // 0..31  (B row within slab)
    int bc0  = (tid & 7) * 8;    // B col base (8 floats each)

    bool arow_ok = (blockM + ar) < M;
    const float* Arow = A + (size_t)(blockM + ar) * K + ac0;
    const float* Bcol = B + blockN + bc0;

    float av[16], bv[8];

    // prefetch slab 0
    #pragma unroll
    for (int j = 0; j < 4; j++) {
        float4 t = make_float4(0,0,0,0);
        if (arow_ok) t = *(const float4*)(Arow + j * 4);
        av[j*4+0]=t.x; av[j*4+1]=t.y; av[j*4+2]=t.z; av[j*4+3]=t.w;
    }
    #pragma unroll
    for (int j = 0; j < 2; j++) {
        float4 t = *(const float4*)(Bcol + (size_t)brow * N + j * 4);
        bv[j*4+0]=t.x; bv[j*4+1]=t.y; bv[j*4+2]=t.z; bv[j*4+3]=t.w;
    }

    float acc[2][4][4];
    #pragma unroll
    for (int mt = 0; mt < 2; mt++)
        #pragma unroll
        for (int nt = 0; nt < 4; nt++)
            #pragma unroll
            for (int i = 0; i < 4; i++) acc[mt][nt][i] = 0.f;

    for (int k0 = 0; k0 < K; k0 += 32) {
        __syncthreads();
        // store current slab (tf32-rounded)
        #pragma unroll
        for (int j = 0; j < 4; j++) {
            float4 s;
            s.x = __uint_as_float(tf32_of(av[j*4+0]));
            s.y = __uint_as_float(tf32_of(av[j*4+1]));
            s.z = __uint_as_float(tf32_of(av[j*4+2]));
            s.w = __uint_as_float(tf32_of(av[j*4+3]));
            *(float4*)&As[ar * ASTR + ac0 + j * 4] = s;
        }
        #pragma unroll
        for (int j = 0; j < 2; j++) {
            float4 s;
            s.x = __uint_as_float(tf32_of(bv[j*4+0]));
            s.y = __uint_as_float(tf32_of(bv[j*4+1]));
            s.z = __uint_as_float(tf32_of(bv[j*4+2]));
            s.w = __uint_as_float(tf32_of(bv[j*4+3]));
            *(float4*)&Bs[brow * BSTR + bc0 + j * 4] = s;
        }
        __syncthreads();

        // prefetch next slab while mma runs
        if (k0 + 32 < K) {
            #pragma unroll
            for (int j = 0; j < 4; j++) {
                float4 t = make_float4(0,0,0,0);
                if (arow_ok) t = *(const float4*)(Arow + k0 + 32 + j * 4);
                av[j*4+0]=t.x; av[j*4+1]=t.y; av[j*4+2]=t.z; av[j*4+3]=t.w;
            }
            #pragma unroll
            for (int j = 0; j < 2; j++) {
                float4 t = *(const float4*)(Bcol + (size_t)(k0 + 32 + brow) * N + j * 4);
                bv[j*4+0]=t.x; bv[j*4+1]=t.y; bv[j*4+2]=t.z; bv[j*4+3]=t.w;
            }
        }

        #pragma unroll
        for (int ks = 0; ks < 4; ks++) {
            unsigned a[2][4], b[4][2];
            #pragma unroll
            for (int mt = 0; mt < 2; mt++) {
                const float* ab = &As[(wm * 32 + mt * 16 + grp) * ASTR + ks * 8 + tig];
                a[mt][0] = __float_as_uint(ab[0]);
                a[mt][1] = __float_as_uint(ab[8 * ASTR]);
                a[mt][2] = __float_as_uint(ab[4]);
                a[mt][3] = __float_as_uint(ab[8 * ASTR + 4]);
            }
            #pragma unroll
            for (int nt = 0; nt < 4; nt++) {
                const float* bb = &Bs[(ks * 8 + tig) * BSTR + wn * 32 + nt * 8 + grp];
                b[nt][0] = __float_as_uint(bb[0]);
                b[nt][1] = __float_as_uint(bb[4 * BSTR]);
            }
            #pragma unroll
            for (int mt = 0; mt < 2; mt++)
                #pragma unroll
                for (int nt = 0; nt < 4; nt++) {
                    asm volatile(
                        "mma.sync.aligned.m16n8k8.row.col.f32.tf32.tf32.f32 "
                        "{%0,%1,%2,%3}, {%4,%5,%6,%7}, {%8,%9}, {%0,%1,%2,%3};\n"
                        : "+f"(acc[mt][nt][0]), "+f"(acc[mt][nt][1]),
                          "+f"(acc[mt][nt][2]), "+f"(acc[mt][nt][3])
                        : "r"(a[mt][0]), "r"(a[mt][1]), "r"(a[mt][2]), "r"(a[mt][3]),
                          "r"(b[nt][0]), "r"(b[nt][1]));
                }
        }
    }

    // epilogue
    #pragma unroll
    for (int mt = 0; mt < 2; mt++) {
        int row0 = blockM + wm * 32 + mt * 16 + grp;
        int row1 = row0 + 8;
        #pragma unroll
        for (int nt = 0; nt < 4; nt++) {
            int col = blockN + wn * 32 + nt * 8 + tig * 2;
            float bx = 0.f, by = 0.f;
            if (bias) { bx = bias[col]; by = bias[col + 1]; }
            float v0 = acc[mt][nt][0] + bx, v1 = acc[mt][nt][1] + by;
            float v2 = acc[mt][nt][2] + bx, v3 = acc[mt][nt][3] + by;
            if (act == 1) {
                v0 = fmaxf(v0, 0.f); v1 = fmaxf(v1, 0.f);
                v2 = fmaxf(v2, 0.f); v3 = fmaxf(v3, 0.f);
            }
            if (row0 < M) { float2 o; o.x = v0; o.y = v1; *(float2*)&C[(size_t)row0 * N + col] = o; }
            if (row1 < M) { float2 o; o.x = v2; o.y = v3; *(float2*)&C[(size_t)row1 * N + col] = o; }
        }
    }
}

// ---------------------------------------------------------------------------
// Final GEMM: C[M,8] = relu(A[M,K] @ B[K,8] + bias). One warp per row.
// ---------------------------------------------------------------------------
__global__ void gemm_n8(const float* __restrict__ A, const float* __restrict__ B,
                        const float* __restrict__ bias, float* __restrict__ C,
                        int M, int K)
{
    int w = (blockIdx.x * blockDim.x + threadIdx.x) >> 5;
    int lane = threadIdx.x & 31;
    if (w >= M) return;
    float a0=0,a1=0,a2=0,a3=0,a4=0,a5=0,a6=0,a7=0;
    for (int k = lane; k < K; k += 32) {
        float a = A[(size_t)w * K + k];
        const float4* bp = (const float4*)(B + k * 8);
        float4 b0 = bp[0], b1 = bp[1];
        a0 += a * b0.x; a1 += a * b0.y; a2 += a * b0.z; a3 += a * b0.w;
        a4 += a * b1.x; a5 += a * b1.y; a6 += a * b1.z; a7 += a * b1.w;
    }
    #pragma unroll
    for (int off = 16; off; off >>= 1) {
        a0 += __shfl_xor_sync(0xffffffffu, a0, off);
        a1 += __shfl_xor_sync(0xffffffffu, a1, off);
        a2 += __shfl_xor_sync(0xffffffffu, a2, off);
        a3 += __shfl_xor_sync(0xffffffffu, a3, off);
        a4 += __shfl_xor_sync(0xffffffffu, a4, off);
        a5 += __shfl_xor_sync(0xffffffffu, a5, off);
        a6 += __shfl_xor_sync(0xffffffffu, a6, off);
        a7 += __shfl_xor_sync(0xffffffffu, a7, off);
    }
    if (lane == 0) {
        float* o = C + (size_t)w * 8;
        o[0] = fmaxf(a0 + bias[0], 0.f); o[1] = fmaxf(a1 + bias[1], 0.f);
        o[2] = fmaxf(a2 + bias[2], 0.f); o[3] = fmaxf(a3 + bias[3], 0.f);
        o[4] = fmaxf(a4 + bias[4], 0.f); o[5] = fmaxf(a5 + bias[5], 0.f);
        o[6] = fmaxf(a6 + bias[6], 0.f); o[7] = fmaxf(a7 + bias[7], 0.f);
    }
}

// ---------------------------------------------------------------------------
// attention dot products (warp per node)
// ---------------------------------------------------------------------------
__global__ void attn_dots(const float* __restrict__ hfeat,
                          const float* __restrict__ attS, const float* __restrict__ attD,
                          float* __restrict__ asrc, float* __restrict__ adst,
                          int Nn, int heads)
{
    int w = (blockIdx.x * blockDim.x + threadIdx.x) >> 5;
    int lane = threadIdx.x & 31;
    if (w >= Nn) return;
    const float4* row = (const float4*)(hfeat + (size_t)w * heads * 128);
    for (int hd = 0; hd < heads; hd++) {
        float4 v  = row[hd * 32 + lane];
        float4 s4 = ((const float4*)attS)[hd * 32 + lane];
        float4 d4 = ((const float4*)attD)[hd * 32 + lane];
        float ps = v.x * s4.x + v.y * s4.y + v.z * s4.z + v.w * s4.w;
        float pd = v.x * d4.x + v.y * d4.y + v.z * d4.z + v.w * d4.w;
        #pragma unroll
        for (int off = 16; off; off >>= 1) {
            ps += __shfl_xor_sync(0xffffffffu, ps, off);
            pd += __shfl_xor_sync(0xffffffffu, pd, off);
        }
        if (lane == 0) {
            asrc[w * heads + hd] = ps;
            adst[w * heads + hd] = pd;
        }
    }
}

// ---------------------------------------------------------------------------
// GAT aggregation, 2 heads (layer 1). Warp per dst node.
// ---------------------------------------------------------------------------
__global__ void agg_gat_h2(const float* __restrict__ hfeat,
                           const float* __restrict__ asrc, const float* __restrict__ adst,
                           const int* __restrict__ srcs, const int* __restrict__ base,
                           const int* __restrict__ cnt, const float* __restrict__ bias,
                           float* __restrict__ out, int Nn)
{
    int n = (blockIdx.x * blockDim.x + threadIdx.x) >> 5;
    int lane = threadIdx.x & 31;
    if (n >= Nn) return;
    int st = base[n], deg = cnt[n];
    float ad0 = adst[2 * n], ad1 = adst[2 * n + 1];

    float m0 = -1e30f, m1 = -1e30f;
    for (int k = lane; k < deg; k += 32) {
        int s = srcs[st + k];
        float2 as = *(const float2*)(asrc + 2 * s);
        m0 = fmaxf(m0, lrelu(as.x + ad0));
        m1 = fmaxf(m1, lrelu(as.y + ad1));
    }
    #pragma unroll
    for (int off = 16; off; off >>= 1) {
        m0 = fmaxf(m0, __shfl_xor_sync(0xffffffffu, m0, off));
        m1 = fmaxf(m1, __shfl_xor_sync(0xffffffffu, m1, off));
    }
    float2 asn = *(const float2*)(asrc + 2 * n);
    float es0 = lrelu(asn.x + ad0), es1 = lrelu(asn.y + ad1);
    m0 = fmaxf(m0, es0); m1 = fmaxf(m1, es1);

    float den0 = 0.f, den1 = 0.f;
    float x0=0,x1=0,x2=0,x3=0, y0=0,y1=0,y2=0,y3=0;
    for (int k = 0; k < deg; k++) {
        int s = __ldg(&srcs[st + k]);
        float2 as = *(const float2*)(asrc + 2 * s);
        float w0 = expf(lrelu(as.x + ad0) - m0);
        float w1 = expf(lrelu(as.y + ad1) - m1);
        den0 += w0; den1 += w1;
        const float4* r = (const float4*)(hfeat + (size_t)s * 256);
        float4 v0 = r[lane];
        float4 v1 = r[32 + lane];
        x0 += w0 * v0.x; x1 += w0 * v0.y; x2 += w0 * v0.z; x3 += w0 * v0.w;
        y0 += w1 * v1.x; y1 += w1 * v1.y; y2 += w1 * v1.z; y3 += w1 * v1.w;
    }
    {
        float w0 = expf(es0 - m0), w1 = expf(es1 - m1);
        den0 += w0; den1 += w1;
        const float4* r = (const float4*)(hfeat + (size_t)n * 256);
        float4 v0 = r[lane];
        float4 v1 = r[32 + lane];
        x0 += w0 * v0.x; x1 += w0 * v0.y; x2 += w0 * v0.z; x3 += w0 * v0.w;
        y0 += w1 * v1.x; y1 += w1 * v1.y; y2 += w1 * v1.z; y3 += w1 * v1.w;
    }
    float i0 = 1.f / fmaxf(den0, 1e-16f);
    float i1 = 1.f / fmaxf(den1, 1e-16f);
    float4 b0 = ((const float4*)bias)[lane];
    float4 b1 = ((const float4*)bias)[32 + lane];
    float4 o0, o1;
    o0.x = elu_f(x0 * i0 + b0.x); o0.y = elu_f(x1 * i0 + b0.y);
    o0.z = elu_f(x2 * i0 + b0.z); o0.w = elu_f(x3 * i0 + b0.w);
    o1.x = elu_f(y0 * i1 + b1.x); o1.y = elu_f(y1 * i1 + b1.y);
    o1.z = elu_f(y2 * i1 + b1.z); o1.w = elu_f(y3 * i1 + b1.w);
    float4* orow = (float4*)(out + (size_t)n * 256);
    orow[lane] = o0;
    orow[32 + lane] = o1;
}

// ---------------------------------------------------------------------------
// GAT aggregation, 1 head (layer 2). Warp per dst node.
// ---------------------------------------------------------------------------
__global__ void agg_gat_h1(const float* __restrict__ hfeat,
                           const float* __restrict__ asrc, const float* __restrict__ adst,
                           const int* __restrict__ srcs, const int* __restrict__ base,
                           const int* __restrict__ cnt, const float* __restrict__ bias,
                           float* __restrict__ out, int Nn)
{
    int n = (blockIdx.x * blockDim.x + threadIdx.x) >> 5;
    int lane = threadIdx.x & 31;
    if (n >= Nn) return;
    int st = base[n], deg = cnt[n];
    float ad = adst[n];

    float m = -1e30f;
    for (int k = lane; k < deg; k += 32) {
        int s = srcs[st + k];
        m = fmaxf(m, lrelu(asrc[s] + ad));
    }
    #pragma unroll
    for (int off = 16; off; off >>= 1)
        m = fmaxf(m, __shfl_xor_sync(0xffffffffu, m, off));
    float es = lrelu(asrc[n] + ad);
    m = fmaxf(m, es);

    float den = 0.f;
    float x0=0,x1=0,x2=0,x3=0;
    for (int k = 0; k < deg; k++) {
        int s = __ldg(&srcs[st + k]);
        float w = expf(lrelu(asrc[s] + ad) - m);
        den += w;
        float4 v = ((const float4*)(hfeat + (size_t)s * 128))[lane];
        x0 += w * v.x; x1 += w * v.y; x2 += w * v.z; x3 += w * v.w;
    }
    {
        float w = expf(es - m);
        den += w;
        float4 v = ((const float4*)(hfeat + (size_t)n * 128))[lane];
        x0 += w * v.x; x1 += w * v.y; x2 += w * v.z; x3 += w * v.w;
    }
    float inv = 1.f / fmaxf(den, 1e-16f);
    float4 b = ((const float4*)bias)[lane];
    float4 o;
    o.x = elu_f(x0 * inv + b.x); o.y = elu_f(x1 * inv + b.y);
    o.z = elu_f(x2 * inv + b.z); o.w = elu_f(x3 * inv + b.w);
    ((float4*)(out + (size_t)n * 128))[lane] = o;
}

// ---------------------------------------------------------------------------
// launch
// ---------------------------------------------------------------------------
extern "C" void kernel_launch(void* const* d_in, const int* in_sizes, int n_in,
                              void* d_out, int out_size)
{
    const float* x        = (const float*)d_in[0];
    const int*   ei       = (const int*)  d_in[1];
    const float* W1       = (const float*)d_in[2];
    const float* att1_src = (const float*)d_in[3];
    const float* att1_dst = (const float*)d_in[4];
    const float* b1       = (const float*)d_in[5];
    const float* W2       = (const float*)d_in[6];
    const float* att2_src = (const float*)d_in[7];
    const float* att2_dst = (const float*)d_in[8];
    const float* b2       = (const float*)d_in[9];
    const float* Wm1      = (const float*)d_in[10];
    const float* bm1      = (const float*)d_in[11];
    const float* Wm2      = (const float*)d_in[12];
    const float* bm2      = (const float*)d_in[13];
    float* out = (float*)d_out;

    int Nn = in_sizes[0] / 128;
    int E  = in_sizes[1] / 2;

    static float *p_h1=nullptr,*p_out1,*p_h2,*p_out2,*p_h3,*p_as1,*p_ad1,*p_as2,*p_ad2;
    static int *p_cnt,*p_base,*p_cur,*p_srcs;
    if (!p_h1) {
        cudaGetSymbolAddress((void**)&p_h1,   g_h1);
        cudaGetSymbolAddress((void**)&p_out1, g_out1);
        cudaGetSymbolAddress((void**)&p_h2,   g_h2);
        cudaGetSymbolAddress((void**)&p_out2, g_out2);
        cudaGetSymbolAddress((void**)&p_h3,   g_h3);
        cudaGetSymbolAddress((void**)&p_as1,  g_as1);
        cudaGetSymbolAddress((void**)&p_ad1,  g_ad1);
        cudaGetSymbolAddress((void**)&p_as2,  g_as2);
        cudaGetSymbolAddress((void**)&p_ad2,  g_ad2);
        cudaGetSymbolAddress((void**)&p_cnt,  g_cnt);
        cudaGetSymbolAddress((void**)&p_base, g_base);
        cudaGetSymbolAddress((void**)&p_cur,  g_cur);
        cudaGetSymbolAddress((void**)&p_srcs, g_srcs);
    }

    int gN   = (Nn + 255) / 256;
    int gE   = (E + 255) / 256;
    int gWrp = (Nn + 7) / 8;

    // CSR build by dst
    zero_counts   <<<gN, 256>>>(p_cnt, p_cur, Nn);
    hist_kernel   <<<gE, 256>>>(ei, E, p_cnt);
    scan_kernel   <<<1, 1024>>>(p_cnt, p_base, Nn);
    scatter_kernel<<<gE, 256>>>(ei, E, p_base, p_cur, p_srcs);

    int mBlocks = (Nn + 127) / 128;

    // Layer 1: GAT(128 -> 2x128, concat)
    gemm_tf32<<<dim3(256 / 64, mBlocks), 256>>>(x, W1, nullptr, p_h1, Nn, 256, 128, 0);
    attn_dots <<<gWrp, 256>>>(p_h1, att1_src, att1_dst, p_as1, p_ad1, Nn, 2);
    agg_gat_h2<<<gWrp, 256>>>(p_h1, p_as1, p_ad1, p_srcs, p_base, p_cnt, b1, p_out1, Nn);

    // Layer 2: GAT(256 -> 128, 1 head)
    gemm_tf32<<<dim3(128 / 64, mBlocks), 256>>>(p_out1, W2, nullptr, p_h2, Nn, 128, 256, 0);
    attn_dots <<<gWrp, 256>>>(p_h2, att2_src, att2_dst, p_as2, p_ad2, Nn, 1);
    agg_gat_h1<<<gWrp, 256>>>(p_h2, p_as2, p_ad2, p_srcs, p_base, p_cnt, b2, p_out2, Nn);

    // MLP head
    gemm_tf32<<<dim3(128 / 64, mBlocks), 256>>>(p_out2, Wm1, bm1, p_h3, Nn, 128, 128, 1);
    gemm_n8<<<gWrp, 256>>>(p_h3, Wm2, bm2, out, Nn, 128);
}